// round 12
// baseline (speedup 1.0000x reference)
#include <cuda_runtime.h>
#include <stdint.h>

// Problem constants (fixed by the dataset: B=4, H=376, W=1241, C=64)
#define BATCH   4
#define HH      376
#define WW      1241
#define CC      64
#define HW      (HH * WW)          // 466616  (divisible by 4)
#define NUM_PIX (BATCH * HW)       // 1866464
#define NPIX4   (NUM_PIX / 4)      // 466616
#define NCOL    ((NPIX4 + 31) / 32)   // 14582 columns of 32 pixel-groups

// Scratch: packed (depth_bits<<32 | point_index) per pixel. ~14.9 MB.
__device__ unsigned long long g_keys[NUM_PIX];

// ---------------------------------------------------------------------------
// Projection matrix P = K @ R @ V2P computed inline (identical instruction
// sequence in every thread -> bitwise-identical P everywhere).
// R = [[0,-1,0],[0,0,-1],[1,0,0]]: (K@R)[i] = ( K[i][2], -K[i][0], -K[i][1] )
// ---------------------------------------------------------------------------
__device__ __forceinline__ void compute_P(const float* __restrict__ K, float* P) {
    const float vv = 0.75f;
    const float xo = 0.375f;     // 0.75/2 + 0
    const float yo = -24.625f;   // 0.75/2 - 25
    const float zo = -24.625f;   // 0.75/2 - 25
    #pragma unroll
    for (int i = 0; i < 3; i++) {
        float a =  __ldg(K + i*3 + 2);
        float b = -__ldg(K + i*3 + 0);
        float c = -__ldg(K + i*3 + 1);
        P[i*4+0] = a * vv;
        P[i*4+1] = b * vv;
        P[i*4+2] = c * vv;
        P[i*4+3] = a*xo + b*yo + c*zo;
    }
}

// ---------------------------------------------------------------------------
// Kernel 1: per-point projection + 64-bit packed atomicMin z-buffer.
// (depth_bits<<32 | index): positive-float bits are order-preserving, so one
// atomic gives min-depth with min-index tie-break, matching the reference.
// ---------------------------------------------------------------------------
__global__ void k_scatter(const int* __restrict__ coords,
                          const float* __restrict__ K, int N) {
    int i = blockIdx.x * blockDim.x + threadIdx.x;
    if (i >= N) return;

    float P[12];
    compute_P(K, P);

    int4 c = reinterpret_cast<const int4*>(coords)[i];  // (b, z, y, x)
    float x = (float)c.w;
    float y = (float)c.z;
    float z = (float)c.y;

    float p0 = fmaf(P[0], x, fmaf(P[1], y, fmaf(P[2],  z, P[3])));
    float p1 = fmaf(P[4], x, fmaf(P[5], y, fmaf(P[6],  z, P[7])));
    float d  = fmaf(P[8], x, fmaf(P[9], y, fmaf(P[10], z, P[11])));

    if (d > 1e-6f) {
        // IEEE division so floor boundaries match the fp32 reference
        int u = (int)floorf(__fdiv_rn(p0, d));
        int v = (int)floorf(__fdiv_rn(p1, d));
        if (u >= 0 && u < WW && v >= 0 && v < HH) {
            int pix = c.x * HW + v * WW + u;
            unsigned long long key =
                ((unsigned long long)__float_as_uint(d) << 32) | (unsigned int)i;
            atomicMin(&g_keys[pix], key);
        }
    }
}

// ---------------------------------------------------------------------------
// Kernel 2: fused resolve + gather (barrier-free).
// One thread = TWO channel quads (cq, cq+8) x 4 consecutive pixels, processed
// SEQUENTIALLY (load A -> store A -> load B -> store B) so only 4 float4s are
// live at once. __launch_bounds__(256, 8) pins regs <= 32 -> 8 blocks/SM ->
// 100% theoretical occupancy; the extra resident warps restore aggregate MLP.
// Stores are fire-and-forget so the serialization doesn't stall the memory
// system. cq==0 warps also emit the inv_depth plane.
// Output layout: [B*C*HW] features then [B*HW] inv_depth.
// ---------------------------------------------------------------------------
__global__ void __launch_bounds__(256, 8)
k_gather(const float* __restrict__ feats, float* __restrict__ out) {
    int i   = blockIdx.x * blockDim.x + threadIdx.x;
    int wid = i >> 5;
    int gl  = i & 31;
    int cq  = wid & 7;           // first channel quad 0..7 (second = cq+8)
    int col = wid >> 3;          // column of 32 pixel-groups
    int pg  = col * 32 + gl;     // global 4-pixel group
    if (pg >= NPIX4) return;

    const ulonglong2* kp = reinterpret_cast<const ulonglong2*>(g_keys) + 2 * pg;
    ulonglong2 ka = __ldg(kp);
    ulonglong2 kb = __ldg(kp + 1);
    // sentinel low word = 0xFFFFFFFF -> -1; winners are small non-negative.
    int w0 = (int)(unsigned)ka.x;
    int w1 = (int)(unsigned)ka.y;
    int w2 = (int)(unsigned)kb.x;
    int w3 = (int)(unsigned)kb.y;

    int p0 = pg * 4;
    int b  = p0 / HW;            // group never crosses batch (HW % 4 == 0)
    int r  = p0 - b * HW;

    if (cq == 0) {
        float4 inv;
        inv.x = (w0 >= 0) ? __fdiv_rn(1.0f, __uint_as_float((unsigned)(ka.x >> 32))) : 0.0f;
        inv.y = (w1 >= 0) ? __fdiv_rn(1.0f, __uint_as_float((unsigned)(ka.y >> 32))) : 0.0f;
        inv.z = (w2 >= 0) ? __fdiv_rn(1.0f, __uint_as_float((unsigned)(kb.x >> 32))) : 0.0f;
        inv.w = (w3 >= 0) ? __fdiv_rn(1.0f, __uint_as_float((unsigned)(kb.y >> 32))) : 0.0f;
        __stcs(reinterpret_cast<float4*>(out + (size_t)NUM_PIX * CC) + pg, inv);
    }

    const float4 zero = make_float4(0.f, 0.f, 0.f, 0.f);
    const float4* frow0 = reinterpret_cast<const float4*>(feats + (size_t)w0 * CC);
    const float4* frow1 = reinterpret_cast<const float4*>(feats + (size_t)w1 * CC);
    const float4* frow2 = reinterpret_cast<const float4*>(feats + (size_t)w2 * CC);
    const float4* frow3 = reinterpret_cast<const float4*>(feats + (size_t)w3 * CC);

    float* opa = out + (size_t)(b * CC + 4 * cq) * HW + r;

    // ---- Quad A (channels 4*cq .. 4*cq+3) ----
    {
        float4 f0 = (w0 >= 0) ? __ldg(frow0 + cq) : zero;
        float4 f1 = (w1 >= 0) ? __ldg(frow1 + cq) : zero;
        float4 f2 = (w2 >= 0) ? __ldg(frow2 + cq) : zero;
        float4 f3 = (w3 >= 0) ? __ldg(frow3 + cq) : zero;
        float4 o;
        #pragma unroll
        for (int k = 0; k < 4; k++) {
            o.x = (&f0.x)[k]; o.y = (&f1.x)[k]; o.z = (&f2.x)[k]; o.w = (&f3.x)[k];
            __stcs(reinterpret_cast<float4*>(opa + (size_t)k * HW), o);
        }
    }
    // ---- Quad B (channels 4*cq+32 .. 4*cq+35) ----
    {
        float* opb = opa + (size_t)32 * HW;
        float4 f0 = (w0 >= 0) ? __ldg(frow0 + cq + 8) : zero;
        float4 f1 = (w1 >= 0) ? __ldg(frow1 + cq + 8) : zero;
        float4 f2 = (w2 >= 0) ? __ldg(frow2 + cq + 8) : zero;
        float4 f3 = (w3 >= 0) ? __ldg(frow3 + cq + 8) : zero;
        float4 o;
        #pragma unroll
        for (int k = 0; k < 4; k++) {
            o.x = (&f0.x)[k]; o.y = (&f1.x)[k]; o.z = (&f2.x)[k]; o.w = (&f3.x)[k];
            __stcs(reinterpret_cast<float4*>(opb + (size_t)k * HW), o);
        }
    }
}

// ---------------------------------------------------------------------------
extern "C" void kernel_launch(void* const* d_in, const int* in_sizes, int n_in,
                              void* d_out, int out_size) {
    const float* feats  = (const float*)d_in[0];   // (N, 64) f32
    const int*   coords = (const int*)d_in[1];     // (N, 4)  i32
    const float* K      = (const float*)d_in[2];   // (3, 3)  f32

    int N = in_sizes[0] / CC;
    float* out = (float*)d_out;

    // Sentinel fill via memset (0xFF bytes == all-ones keys).
    void* keys_ptr = nullptr;
    cudaGetSymbolAddress(&keys_ptr, g_keys);
    cudaMemsetAsync(keys_ptr, 0xFF, sizeof(unsigned long long) * NUM_PIX);

    const int T = 256;
    k_scatter<<<(N + T - 1) / T, T>>>(coords, K, N);

    // 8 dual-quad warps per 32-group column; 8 warps per block.
    k_gather<<<NCOL, T>>>(feats, out);
}